// round 1
// baseline (speedup 1.0000x reference)
#include <cuda_runtime.h>

#define NN      131072
#define NG      256
#define INDIM   256
#define HID     512
#define HID2    1024
#define NE      2097152
#define OFF_L   ((size_t)NN * INDIM)      /* 33554432 : logits section   */
#define OFF_E   (OFF_L + NN)              /* 33685504 : edge-mask section */

// -------- scratch (device globals: allocation-free per harness rules) ------
__device__ float         g_z[(size_t)NN * HID2];   // 512 MB GEMM output
__device__ float         g_logits[NN];
__device__ unsigned char g_keep[NN];
__device__ int           g_start[NG + 1];

// -------- packed fp32x2 helpers (Blackwell sm_103a) -------------------------
__device__ __forceinline__ unsigned long long pack2(float a, float b) {
    unsigned long long r;
    asm("mov.b64 %0, {%1,%2};" : "=l"(r) : "f"(a), "f"(b));
    return r;
}
__device__ __forceinline__ void fma2(unsigned long long& d,
                                     unsigned long long a, unsigned long long b) {
    asm("fma.rn.f32x2 %0, %1, %2, %0;" : "+l"(d) : "l"(a), "l"(b));
}
__device__ __forceinline__ float2 unpack2(unsigned long long v) {
    float2 r;
    asm("mov.b64 {%0,%1}, %2;" : "=f"(r.x), "=f"(r.y) : "l"(v));
    return r;
}

// ============================================================================
// Kernel 1: z = h @ W1 + b1   (131072x512 @ 512x1024, fp32, f32x2 pipe)
// Tile 128x128x16, 256 threads, 8x8 per-thread microtile as 8x4 f32x2 accums.
// A staged into smem transposed AND duplicated: As[k][2m]=As[k][2m+1]=A[m][k],
// so the broadcast operand for fma.rn.f32x2 is a plain LDS.128.
// ============================================================================
__device__ __forceinline__ void storeA_dup(float (*Asb)[256], int kk, int row, float4 v) {
    *(unsigned long long*)&Asb[kk + 0][2 * row] = pack2(v.x, v.x);
    *(unsigned long long*)&Asb[kk + 1][2 * row] = pack2(v.y, v.y);
    *(unsigned long long*)&Asb[kk + 2][2 * row] = pack2(v.z, v.z);
    *(unsigned long long*)&Asb[kk + 3][2 * row] = pack2(v.w, v.w);
}

__global__ __launch_bounds__(256, 2) void gemm1_kernel(
    const float* __restrict__ A,      // h  [NN, 512]
    const float* __restrict__ B,      // W1 [512, 1024]
    const float* __restrict__ bias)   // b1 [1024]
{
    __shared__ __align__(16) float As[2][16][256];
    __shared__ __align__(16) float Bs[2][16][132];

    const int tid = threadIdx.x;
    const int bn = blockIdx.x;        // 8 tiles of N=1024
    const int bm = blockIdx.y;        // 1024 tiles of M=131072
    const int tx = tid & 15, ty = tid >> 4;

    // global-load assignments (2x float4 each for A and B per K-iter)
    const int f0 = tid * 2, f1 = f0 + 1;
    const int ar0 = f0 >> 2, ak0 = (f0 & 3) << 2;
    const int ar1 = f1 >> 2, ak1 = (f1 & 3) << 2;
    const int bk0 = f0 >> 5, bn0 = (f0 & 31) << 2;
    const int bk1 = f1 >> 5, bn1 = (f1 & 31) << 2;

    const float* Ag0 = A + ((size_t)(bm * 128 + ar0)) * HID + ak0;
    const float* Ag1 = A + ((size_t)(bm * 128 + ar1)) * HID + ak1;
    const float* Bg0 = B + (size_t)bk0 * HID2 + bn * 128 + bn0;
    const float* Bg1 = B + (size_t)bk1 * HID2 + bn * 128 + bn1;

    unsigned long long acc[8][4] = {};   // (c[i][2j], c[i][2j+1]) pairs, = 0.0f bits

    float4 va0 = *(const float4*)Ag0;
    float4 va1 = *(const float4*)Ag1;
    float4 vb0 = *(const float4*)Bg0;
    float4 vb1 = *(const float4*)Bg1;

    for (int kt = 0; kt < 32; kt++) {
        const int buf = kt & 1;
        storeA_dup(As[buf], ak0, ar0, va0);
        storeA_dup(As[buf], ak1, ar1, va1);
        *(float4*)&Bs[buf][bk0][bn0] = vb0;
        *(float4*)&Bs[buf][bk1][bn1] = vb1;
        __syncthreads();   // single barrier/iter: store(kt+2,buf) is ordered after
                           // every thread's compute(kt,buf) via sync(kt+1).
        if (kt < 31) {     // register prefetch of next K-tile (hides DRAM latency)
            va0 = *(const float4*)(Ag0 + (kt + 1) * 16);
            va1 = *(const float4*)(Ag1 + (kt + 1) * 16);
            vb0 = *(const float4*)(Bg0 + (size_t)(kt + 1) * 16 * HID2);
            vb1 = *(const float4*)(Bg1 + (size_t)(kt + 1) * 16 * HID2);
        }
        #pragma unroll
        for (int k = 0; k < 16; k++) {
            const ulonglong2* ap = (const ulonglong2*)&As[buf][k][ty * 16];
            const ulonglong2* bp = (const ulonglong2*)&Bs[buf][k][tx * 8];
            ulonglong2 A0 = ap[0], A1 = ap[1], A2 = ap[2], A3 = ap[3];
            ulonglong2 B0 = bp[0], B1 = bp[1];
            unsigned long long av[8] = {A0.x, A0.y, A1.x, A1.y, A2.x, A2.y, A3.x, A3.y};
            unsigned long long bv[4] = {B0.x, B0.y, B1.x, B1.y};
            #pragma unroll
            for (int i = 0; i < 8; i++)
                #pragma unroll
                for (int j = 0; j < 4; j++)
                    fma2(acc[i][j], av[i], bv[j]);
        }
    }

    // epilogue: + bias, store z
    const float* bp = bias + bn * 128 + tx * 8;
    const float4 blo = *(const float4*)bp;
    const float4 bhi = *(const float4*)(bp + 4);
    #pragma unroll
    for (int i = 0; i < 8; i++) {
        float2 c0 = unpack2(acc[i][0]);
        float2 c1 = unpack2(acc[i][1]);
        float2 c2 = unpack2(acc[i][2]);
        float2 c3 = unpack2(acc[i][3]);
        float4 lo = make_float4(c0.x + blo.x, c0.y + blo.y, c1.x + blo.z, c1.y + blo.w);
        float4 hi = make_float4(c2.x + bhi.x, c2.y + bhi.y, c3.x + bhi.z, c3.y + bhi.w);
        const size_t m = (size_t)bm * 128 + ty * 8 + i;
        float* cp = g_z + m * HID2 + bn * 128 + tx * 8;
        *(float4*)cp       = lo;
        *(float4*)(cp + 4) = hi;
    }
}

// ============================================================================
// Kernel 2: per-row LayerNorm -> ReLU -> dot(W2) -> sigmoid.  1 block / row.
// ============================================================================
__device__ __forceinline__ float block_reduce_256(float v, float* sh) {
    #pragma unroll
    for (int o = 16; o > 0; o >>= 1) v += __shfl_down_sync(0xffffffffu, v, o);
    const int lane = threadIdx.x & 31, w = threadIdx.x >> 5;
    if (lane == 0) sh[w] = v;
    __syncthreads();
    if (threadIdx.x < 32) {
        float t = (threadIdx.x < 8) ? sh[threadIdx.x] : 0.0f;
        #pragma unroll
        for (int o = 4; o > 0; o >>= 1) t += __shfl_down_sync(0xffffffffu, t, o);
        if (threadIdx.x == 0) sh[8] = t;
    }
    __syncthreads();
    float r = sh[8];
    __syncthreads();
    return r;
}

__global__ __launch_bounds__(256) void ln_head_kernel(
    const float* __restrict__ gamma, const float* __restrict__ beta,
    const float* __restrict__ W2, const float* __restrict__ b2)
{
    __shared__ float sh[9];
    const size_t row = blockIdx.x;
    const int t = threadIdx.x;
    const float4 v = *((const float4*)(g_z + row * HID2) + t);

    float s = v.x + v.y + v.z + v.w;
    const float mu = block_reduce_256(s, sh) * (1.0f / 1024.0f);

    const float d0 = v.x - mu, d1 = v.y - mu, d2 = v.z - mu, d3 = v.w - mu;
    float sq = d0 * d0 + d1 * d1 + d2 * d2 + d3 * d3;
    const float var = block_reduce_256(sq, sh) * (1.0f / 1024.0f);
    const float rstd = 1.0f / sqrtf(var + 1e-5f);

    const float4 gv = ((const float4*)gamma)[t];
    const float4 bv = ((const float4*)beta)[t];
    const float4 wv = ((const float4*)W2)[t];
    float a = 0.0f, zn;
    zn = d0 * rstd * gv.x + bv.x; if (zn > 0.0f) a += zn * wv.x;
    zn = d1 * rstd * gv.y + bv.y; if (zn > 0.0f) a += zn * wv.y;
    zn = d2 * rstd * gv.z + bv.z; if (zn > 0.0f) a += zn * wv.z;
    zn = d3 * rstd * gv.w + bv.w; if (zn > 0.0f) a += zn * wv.w;
    const float pre = block_reduce_256(a, sh) + b2[0];
    if (t == 0) g_logits[row] = 1.0f / (1.0f + expf(-pre));
}

// ============================================================================
// Kernel 3: segment starts via binary search on sorted batch ids
// ============================================================================
__global__ void seg_starts_kernel(const int* __restrict__ batch) {
    const int g = blockIdx.x * blockDim.x + threadIdx.x;
    if (g > NG) return;
    int lo = 0, hi = NN;
    while (lo < hi) { int mid = (lo + hi) >> 1; if (batch[mid] < g) lo = mid + 1; else hi = mid; }
    g_start[g] = lo;
}

// ============================================================================
// Kernel 4: per-graph top-k keep mask, rank-count formulation.
// Exactly replicates lexsort((-logits, batch)) stable ordering: node i kept iff
// #{j : l_j > l_i  or  (l_j == l_i and j < i)} < ceil(0.9 * n_g).
// ============================================================================
__global__ __launch_bounds__(512) void topk_kernel() {
    __shared__ float sl[1024];
    const int g = blockIdx.x;
    const int s = g_start[g];
    int n = g_start[g + 1] - s;
    if (n > 1024) n = 1024;            // binomial(131072, 1/256): never triggers
    const int k = (9 * n + 9) / 10;    // == ceil(0.9 * n)
    for (int i = threadIdx.x; i < n; i += 512) sl[i] = g_logits[s + i];
    __syncthreads();
    for (int i = threadIdx.x; i < n; i += 512) {
        const float li = sl[i];
        int cnt = 0;
        for (int j = 0; j < n; j++) {
            const float lj = sl[j];
            cnt += (lj > li) || (lj == li && j < i);
        }
        g_keep[s + i] = (cnt < k) ? 1 : 0;
    }
}

// ============================================================================
// Kernel 5: x_new = keep ? x*logit : noise.  One warp stays inside one node
// (64 float4 per node, 32 per warp) -> uniform branch, single-source load.
// ============================================================================
__global__ void finalize_kernel(const float4* __restrict__ x4,
                                const float4* __restrict__ n4,
                                float* __restrict__ out)
{
    const int v = blockIdx.x * blockDim.x + threadIdx.x;   // [0, NN*64)
    const int node = v >> 6;
    const bool kp = g_keep[node] != 0;
    const float4* src = kp ? x4 : n4;
    float4 r = src[v];
    if (kp) { const float l = g_logits[node]; r.x *= l; r.y *= l; r.z *= l; r.w *= l; }
    ((float4*)out)[v] = r;
}

// Kernel 6: logits section + zero edge-mask section
__global__ void tail_kernel(float* __restrict__ out) {
    const int i = blockIdx.x * blockDim.x + threadIdx.x;
    if (i < NN) { out[OFF_L + i] = g_logits[i]; out[OFF_E + i] = 0.0f; }
}

// Kernel 7: edge-touch scatter (idempotent same-value stores; races benign)
__global__ void edge_kernel(const int* __restrict__ ei, float* __restrict__ out) {
    const int e = blockIdx.x * blockDim.x + threadIdx.x;
    if (e < 2 * NE) out[OFF_E + ei[e]] = 1.0f;
}

// ============================================================================
extern "C" void kernel_launch(void* const* d_in, const int* in_sizes, int n_in,
                              void* d_out, int out_size) {
    const float* h     = (const float*)d_in[0];
    const float* x     = (const float*)d_in[1];
    const float* noise = (const float*)d_in[2];
    const float* W1    = (const float*)d_in[3];
    const float* b1    = (const float*)d_in[4];
    const float* gamma = (const float*)d_in[5];
    const float* beta  = (const float*)d_in[6];
    const float* W2    = (const float*)d_in[7];
    const float* b2    = (const float*)d_in[8];
    const int*   batch = (const int*)d_in[9];
    const int*   edges = (const int*)d_in[10];
    float* out = (float*)d_out;
    (void)in_sizes; (void)n_in; (void)out_size;

    gemm1_kernel<<<dim3(8, 1024), 256>>>(h, W1, b1);
    ln_head_kernel<<<NN, 256>>>(gamma, beta, W2, b2);
    seg_starts_kernel<<<1, 512>>>(batch);
    topk_kernel<<<NG, 512>>>();
    finalize_kernel<<<(NN * 64) / 256, 256>>>((const float4*)x, (const float4*)noise, out);
    tail_kernel<<<NN / 256, 256>>>(out);
    edge_kernel<<<(2 * NE) / 256, 256>>>(edges, out);
}